// round 2
// baseline (speedup 1.0000x reference)
#include <cuda_runtime.h>
#include <cuda_bf16.h>
#include <math.h>

// ---------------------------------------------------------------------------
// Encoder layer: N=2, L=2048, D=1024, H=16, HD=64, FF=4096, fp32.
// Tokens T = N*L = 4096.
// Pipeline:
//   qkv  = x @ w_qkv + b_qkv                       [4096, 3072]
//   attn = flash-attention(qkv)                    [4096, 1024]
//   res1 = attn @ w_o + b_o + x                    [4096, 1024]
//   h    = LN(res1, g1, be1)                       [4096, 1024]
//   ff   = relu(h @ w1 + b1)                       [4096, 4096]
//   res2 = ff @ w2 + b2 + h                        [4096, 1024]
//   out  = LN(res2, g2, be2)                       [4096, 1024]
// ---------------------------------------------------------------------------

#define T_TOK 4096
#define DMODEL 1024
#define D3 3072
#define FFDIM 4096
#define NHEAD 16
#define HDIM 64
#define SEQ 2048

// Scratch (allocation-free: __device__ globals)
__device__ float g_qkv [T_TOK * (size_t)D3];
__device__ float g_attn[T_TOK * (size_t)DMODEL];
__device__ float g_res [T_TOK * (size_t)DMODEL];
__device__ float g_h   [T_TOK * (size_t)DMODEL];
__device__ float g_ff  [T_TOK * (size_t)FFDIM];

// ---------------------------------------------------------------------------
// SGEMM: C[M,N] = A[M,K] @ B[K,N] + bias[N]  (+ optional relu / + residual)
// 128x128 block tile, 256 threads, 8x8 microtile per thread (2x2 split of 4x4
// fragments for conflict-free LDS.128), K-tile = 8.
// Requires M%128==0, N%128==0, K%8==0 (true for all shapes here).
// ---------------------------------------------------------------------------
template<bool RELU, bool RES>
__global__ void __launch_bounds__(256) sgemm_kernel(
    const float* __restrict__ A, const float* __restrict__ B,
    const float* __restrict__ bias, const float* __restrict__ res,
    float* __restrict__ C, int M, int N, int K)
{
    __shared__ float As[8][128];   // A^T tile: As[k][m]
    __shared__ float Bs[8][128];   // B tile:   Bs[k][n]

    const int tid = threadIdx.x;
    const int tx  = tid & 15;      // 0..15 (col group)
    const int ty  = tid >> 4;      // 0..15 (row group)
    const int bx  = blockIdx.x;    // along N
    const int by  = blockIdx.y;    // along M

    // global->smem load mapping
    const int a_m = tid >> 1;            // 0..127
    const int a_k = (tid & 1) << 2;      // 0 or 4
    const int b_k = tid >> 5;            // 0..7
    const int b_n = (tid & 31) << 2;     // 0..124

    const float* Ap = A + (size_t)(by * 128 + a_m) * K + a_k;
    const float* Bp = B + (size_t)b_k * N + bx * 128 + b_n;

    float acc[8][8];
#pragma unroll
    for (int i = 0; i < 8; i++)
#pragma unroll
        for (int j = 0; j < 8; j++) acc[i][j] = 0.f;

    for (int k0 = 0; k0 < K; k0 += 8) {
        const float4 av = *(const float4*)(Ap + k0);
        const float4 bv = *(const float4*)(Bp + (size_t)k0 * N);
        __syncthreads();                  // previous tile's compute done
        As[a_k + 0][a_m] = av.x;
        As[a_k + 1][a_m] = av.y;
        As[a_k + 2][a_m] = av.z;
        As[a_k + 3][a_m] = av.w;
        *(float4*)&Bs[b_k][b_n] = bv;
        __syncthreads();

#pragma unroll
        for (int kk = 0; kk < 8; kk++) {
            const float4 a0 = *(const float4*)&As[kk][ty * 4];
            const float4 a1 = *(const float4*)&As[kk][64 + ty * 4];
            const float4 b0 = *(const float4*)&Bs[kk][tx * 4];
            const float4 b1 = *(const float4*)&Bs[kk][64 + tx * 4];
            const float a[8] = {a0.x, a0.y, a0.z, a0.w, a1.x, a1.y, a1.z, a1.w};
            const float b[8] = {b0.x, b0.y, b0.z, b0.w, b1.x, b1.y, b1.z, b1.w};
#pragma unroll
            for (int i = 0; i < 8; i++)
#pragma unroll
                for (int j = 0; j < 8; j++)
                    acc[i][j] = fmaf(a[i], b[j], acc[i][j]);
        }
    }

    // epilogue
#pragma unroll
    for (int i = 0; i < 8; i++) {
        const int gr = by * 128 + ((i < 4) ? (ty * 4 + i) : (64 + ty * 4 + i - 4));
#pragma unroll
        for (int hh = 0; hh < 2; hh++) {
            const int gc = bx * 128 + hh * 64 + tx * 4;
            float4 v;
            v.x = acc[i][hh * 4 + 0] + bias[gc + 0];
            v.y = acc[i][hh * 4 + 1] + bias[gc + 1];
            v.z = acc[i][hh * 4 + 2] + bias[gc + 2];
            v.w = acc[i][hh * 4 + 3] + bias[gc + 3];
            if (RELU) {
                v.x = fmaxf(v.x, 0.f); v.y = fmaxf(v.y, 0.f);
                v.z = fmaxf(v.z, 0.f); v.w = fmaxf(v.w, 0.f);
            }
            if (RES) {
                const float4 r = *(const float4*)(res + (size_t)gr * N + gc);
                v.x += r.x; v.y += r.y; v.z += r.z; v.w += r.w;
            }
            *(float4*)(C + (size_t)gr * N + gc) = v;
        }
    }
}

// ---------------------------------------------------------------------------
// Flash attention, fp32. One block = (batch n, head h, 128 query rows).
// One thread owns one query row (q[64], o[64] in registers, online softmax).
// K/V staged in smem tiles of 64 keys; all compute-side LDS are warp-broadcast.
// grid = 2 * 16 * 16 = 512 blocks, 128 threads.
// ---------------------------------------------------------------------------
__global__ void __launch_bounds__(128) attn_kernel(
    const float* __restrict__ qkv, float* __restrict__ out)
{
    __shared__ float Ks[64][68];   // pad to 68 floats: breaks STS bank pathology
    __shared__ float Vs[64][68];

    const int bid = blockIdx.x;
    const int qt = bid & 15;             // query tile 0..15
    const int h  = (bid >> 4) & 15;      // head
    const int n  = bid >> 8;             // batch
    const int tid = threadIdx.x;
    const int q_idx = qt * 128 + tid;

    const float* qrow = qkv + (size_t)(n * SEQ + q_idx) * D3 + h * HDIM;
    float q[64];
#pragma unroll
    for (int d = 0; d < 64; d += 4) {
        const float4 v = *(const float4*)(qrow + d);
        q[d + 0] = v.x * 0.125f;
        q[d + 1] = v.y * 0.125f;
        q[d + 2] = v.z * 0.125f;
        q[d + 3] = v.w * 0.125f;
    }

    float m = -1e30f, l = 0.f;
    float o[64];
#pragma unroll
    for (int d = 0; d < 64; d++) o[d] = 0.f;

    // K/V tile cooperative-load mapping: 2 threads per key row
    const int jl = tid >> 1;             // key row 0..63
    const int dl = (tid & 1) * 32;       // half-row 0 / 32

    for (int kt = 0; kt < 32; kt++) {
        __syncthreads();                 // smem free to overwrite
        const float* kbase = qkv + (size_t)(n * SEQ + kt * 64 + jl) * D3
                             + DMODEL + h * HDIM + dl;
        const float* vbase = kbase + DMODEL;   // V follows K by D
#pragma unroll
        for (int r = 0; r < 8; r++) {
            *(float4*)&Ks[jl][dl + r * 4] = *(const float4*)(kbase + r * 4);
            *(float4*)&Vs[jl][dl + r * 4] = *(const float4*)(vbase + r * 4);
        }
        __syncthreads();

        for (int j = 0; j < 64; j++) {
            float s = 0.f;
#pragma unroll
            for (int d = 0; d < 64; d += 4) {
                const float4 kv = *(const float4*)&Ks[j][d];
                s = fmaf(q[d + 0], kv.x, s);
                s = fmaf(q[d + 1], kv.y, s);
                s = fmaf(q[d + 2], kv.z, s);
                s = fmaf(q[d + 3], kv.w, s);
            }
            if (s > m) {                 // rare after warmup (~log L times)
                const float c = __expf(m - s);
                l *= c;
#pragma unroll
                for (int d = 0; d < 64; d++) o[d] *= c;
                m = s;
            }
            const float p = __expf(s - m);
            l += p;
#pragma unroll
            for (int d = 0; d < 64; d += 4) {
                const float4 vv = *(const float4*)&Vs[j][d];
                o[d + 0] = fmaf(p, vv.x, o[d + 0]);
                o[d + 1] = fmaf(p, vv.y, o[d + 1]);
                o[d + 2] = fmaf(p, vv.z, o[d + 2]);
                o[d + 3] = fmaf(p, vv.w, o[d + 3]);
            }
        }
    }

    const float inv = 1.f / l;
    float* op = out + (size_t)(n * SEQ + q_idx) * DMODEL + h * HDIM;
#pragma unroll
    for (int d = 0; d < 64; d += 4) {
        float4 v;
        v.x = o[d + 0] * inv; v.y = o[d + 1] * inv;
        v.z = o[d + 2] * inv; v.w = o[d + 3] * inv;
        *(float4*)(op + d) = v;
    }
}

// ---------------------------------------------------------------------------
// LayerNorm over last dim (1024). One block per row, 256 threads x float4.
// ---------------------------------------------------------------------------
__global__ void __launch_bounds__(256) ln_kernel(
    const float* __restrict__ in, const float* __restrict__ gamma,
    const float* __restrict__ beta, float* __restrict__ out)
{
    const int row = blockIdx.x;
    const int tid = threadIdx.x;
    const float4 v = ((const float4*)(in + (size_t)row * DMODEL))[tid];

    float s  = v.x + v.y + v.z + v.w;
    float sq = v.x * v.x + v.y * v.y + v.z * v.z + v.w * v.w;
#pragma unroll
    for (int off = 16; off > 0; off >>= 1) {
        s  += __shfl_xor_sync(0xffffffffu, s,  off);
        sq += __shfl_xor_sync(0xffffffffu, sq, off);
    }
    __shared__ float ss[8], qq[8];
    if ((tid & 31) == 0) { ss[tid >> 5] = s; qq[tid >> 5] = sq; }
    __syncthreads();
    float tot = 0.f, totq = 0.f;
#pragma unroll
    for (int i = 0; i < 8; i++) { tot += ss[i]; totq += qq[i]; }

    const float mu  = tot * (1.f / DMODEL);
    const float var = totq * (1.f / DMODEL) - mu * mu;
    const float rs  = rsqrtf(var + 1e-5f);

    const float4 g = ((const float4*)gamma)[tid];
    const float4 b = ((const float4*)beta)[tid];
    float4 o;
    o.x = (v.x - mu) * rs * g.x + b.x;
    o.y = (v.y - mu) * rs * g.y + b.y;
    o.z = (v.z - mu) * rs * g.z + b.z;
    o.w = (v.w - mu) * rs * g.w + b.w;
    ((float4*)(out + (size_t)row * DMODEL))[tid] = o;
}

// ---------------------------------------------------------------------------
extern "C" void kernel_launch(void* const* d_in, const int* in_sizes, int n_in,
                              void* d_out, int out_size)
{
    (void)in_sizes; (void)n_in; (void)out_size;
    const float* x     = (const float*)d_in[0];
    const float* w_qkv = (const float*)d_in[1];
    const float* b_qkv = (const float*)d_in[2];
    const float* w_o   = (const float*)d_in[3];
    const float* b_o   = (const float*)d_in[4];
    const float* g1    = (const float*)d_in[5];
    const float* be1   = (const float*)d_in[6];
    const float* w1    = (const float*)d_in[7];
    const float* b1    = (const float*)d_in[8];
    const float* w2    = (const float*)d_in[9];
    const float* b2    = (const float*)d_in[10];
    const float* g2    = (const float*)d_in[11];
    const float* be2   = (const float*)d_in[12];
    float* out = (float*)d_out;

    float *qkv, *attn, *res, *h, *ff;
    cudaGetSymbolAddress((void**)&qkv,  g_qkv);
    cudaGetSymbolAddress((void**)&attn, g_attn);
    cudaGetSymbolAddress((void**)&res,  g_res);
    cudaGetSymbolAddress((void**)&h,    g_h);
    cudaGetSymbolAddress((void**)&ff,   g_ff);

    // 1) qkv = x @ w_qkv + b_qkv
    sgemm_kernel<false, false><<<dim3(D3 / 128, T_TOK / 128), 256>>>(
        x, w_qkv, b_qkv, nullptr, qkv, T_TOK, D3, DMODEL);

    // 2) attention
    attn_kernel<<<512, 128>>>(qkv, attn);

    // 3) res1 = attn @ w_o + b_o + x
    sgemm_kernel<false, true><<<dim3(DMODEL / 128, T_TOK / 128), 256>>>(
        attn, w_o, b_o, x, res, T_TOK, DMODEL, DMODEL);

    // 4) h = LN(res1)
    ln_kernel<<<T_TOK, 256>>>(res, g1, be1, h);

    // 5) ff = relu(h @ w1 + b1)
    sgemm_kernel<true, false><<<dim3(FFDIM / 128, T_TOK / 128), 256>>>(
        h, w1, b1, nullptr, ff, T_TOK, FFDIM, DMODEL);

    // 6) res2 = ff @ w2 + b2 + h
    sgemm_kernel<false, true><<<dim3(DMODEL / 128, T_TOK / 128), 256>>>(
        ff, w2, b2, h, res, T_TOK, DMODEL, FFDIM);

    // 7) out = LN(res2)
    ln_kernel<<<T_TOK, 256>>>(res, g2, be2, out);
}

// round 5
// speedup vs baseline: 1.6949x; 1.6949x over previous
#include <cuda_runtime.h>
#include <cuda_bf16.h>
#include <math.h>
#include <stdint.h>

// ---------------------------------------------------------------------------
// Encoder layer: N=2, L=2048, D=1024, H=16, HD=64, FF=4096, fp32 in/out.
// GEMMs: warp-level mma.sync bf16 split-3 (baseline-ISA HMMA — no 'a' features).
// Attention: fp32 (Round-5 target). LN: fused one-pass.
// ---------------------------------------------------------------------------

#define T_TOK 4096
#define DMODEL 1024
#define D3 3072
#define FFDIM 4096
#define SEQ 2048

// Scratch (allocation-free: __device__ globals)
__device__ float g_qkv [T_TOK * (size_t)D3];
__device__ float g_attn[T_TOK * (size_t)DMODEL];
__device__ float g_res [T_TOK * (size_t)DMODEL];
__device__ float g_h   [T_TOK * (size_t)DMODEL];
__device__ float g_ff  [T_TOK * (size_t)FFDIM];
// bf16 hi/lo operand buffers (reused serially across the 4 GEMMs)
__device__ __nv_bfloat16 g_a_hi[T_TOK * (size_t)FFDIM];
__device__ __nv_bfloat16 g_a_lo[T_TOK * (size_t)FFDIM];
__device__ __nv_bfloat16 g_w_hi[(size_t)FFDIM * DMODEL];
__device__ __nv_bfloat16 g_w_lo[(size_t)FFDIM * DMODEL];

// ---------------------------------------------------------------------------
// Baseline-ISA PTX helpers (sm_80+: ldmatrix / mma.sync / cp.async)
// ---------------------------------------------------------------------------
__device__ __forceinline__ uint32_t smem_u32(const void* p) {
    uint32_t a;
    asm("{ .reg .u64 t; cvta.to.shared.u64 t, %1; cvt.u32.u64 %0, t; }"
        : "=r"(a) : "l"(p));
    return a;
}
__device__ __forceinline__ void ldsm_x4(uint32_t& r0, uint32_t& r1,
                                        uint32_t& r2, uint32_t& r3,
                                        uint32_t addr) {
    asm volatile("ldmatrix.sync.aligned.m8n8.x4.shared.b16 {%0,%1,%2,%3}, [%4];"
                 : "=r"(r0), "=r"(r1), "=r"(r2), "=r"(r3) : "r"(addr));
}
__device__ __forceinline__ void mma16816(float* d, const uint32_t* a,
                                         const uint32_t* b) {
    asm volatile(
        "mma.sync.aligned.m16n8k16.row.col.f32.bf16.bf16.f32 "
        "{%0,%1,%2,%3}, {%4,%5,%6,%7}, {%8,%9}, {%0,%1,%2,%3};"
        : "+f"(d[0]), "+f"(d[1]), "+f"(d[2]), "+f"(d[3])
        : "r"(a[0]), "r"(a[1]), "r"(a[2]), "r"(a[3]), "r"(b[0]), "r"(b[1]));
}
__device__ __forceinline__ void cp_async16(uint32_t dst, const void* src) {
    asm volatile("cp.async.cg.shared.global [%0], [%1], 16;"
                 :: "r"(dst), "l"(src));
}
__device__ __forceinline__ void cp_commit() {
    asm volatile("cp.async.commit_group;" ::: "memory");
}
template<int W> __device__ __forceinline__ void cp_wait() {
    asm volatile("cp.async.wait_group %0;" :: "n"(W) : "memory");
}

#define SWZ128(o) ((o) ^ (((o) >> 3) & 0x70))

// ---------------------------------------------------------------------------
// fp32 -> bf16 hi/lo split (row-major passthrough)
// ---------------------------------------------------------------------------
__global__ void __launch_bounds__(256) split_kernel(
    const float* __restrict__ in, __nv_bfloat16* __restrict__ hi,
    __nv_bfloat16* __restrict__ lo, int n4)
{
    int i = blockIdx.x * 256 + threadIdx.x;
    if (i >= n4) return;
    const float4 v = ((const float4*)in)[i];
    __nv_bfloat16 h0 = __float2bfloat16(v.x);
    __nv_bfloat16 h1 = __float2bfloat16(v.y);
    __nv_bfloat16 h2 = __float2bfloat16(v.z);
    __nv_bfloat16 h3 = __float2bfloat16(v.w);
    __nv_bfloat16 l0 = __float2bfloat16(v.x - __bfloat162float(h0));
    __nv_bfloat16 l1 = __float2bfloat16(v.y - __bfloat162float(h1));
    __nv_bfloat16 l2 = __float2bfloat16(v.z - __bfloat162float(h2));
    __nv_bfloat16 l3 = __float2bfloat16(v.w - __bfloat162float(h3));
    ((__nv_bfloat162*)hi)[2 * i + 0] = __nv_bfloat162(h0, h1);
    ((__nv_bfloat162*)hi)[2 * i + 1] = __nv_bfloat162(h2, h3);
    ((__nv_bfloat162*)lo)[2 * i + 0] = __nv_bfloat162(l0, l1);
    ((__nv_bfloat162*)lo)[2 * i + 1] = __nv_bfloat162(l2, l3);
}

// ---------------------------------------------------------------------------
// Weight transpose + split: in [Kd, Nd] fp32 -> hi/lo [Nd, Kd] bf16
// ---------------------------------------------------------------------------
__global__ void __launch_bounds__(256) tsplit_kernel(
    const float* __restrict__ in, __nv_bfloat16* __restrict__ hi,
    __nv_bfloat16* __restrict__ lo, int Kd, int Nd)
{
    __shared__ float t[32][33];
    const int n0 = blockIdx.x * 32, k0 = blockIdx.y * 32;
    const int tx = threadIdx.x, ty = threadIdx.y;
#pragma unroll
    for (int r = 0; r < 32; r += 8)
        t[ty + r][tx] = in[(size_t)(k0 + ty + r) * Nd + n0 + tx];
    __syncthreads();
#pragma unroll
    for (int r = 0; r < 32; r += 8) {
        const float v = t[tx][ty + r];
        const __nv_bfloat16 h = __float2bfloat16(v);
        const __nv_bfloat16 l = __float2bfloat16(v - __bfloat162float(h));
        const size_t o = (size_t)(n0 + ty + r) * Kd + k0 + tx;
        hi[o] = h;
        lo[o] = l;
    }
}

// ---------------------------------------------------------------------------
// bf16 split-3 GEMM via mma.sync: C[M,N] = A @ W^T + bias (+relu / +res)
// Ah/Al [M,K] bf16 K-major; Bh/Bl [N,K] bf16 K-major.
// CTA tile 128x128, 8 warps (2x4), warp tile 64x32, K-chunk 64.
// 2-stage cp.async pipeline, SW128-swizzled smem, conflict-free ldmatrix.
// ---------------------------------------------------------------------------
#define GEMM_SMEM_BYTES (2 * 65536)

template<bool RELU, bool RES>
__global__ void __launch_bounds__(256, 1) gemm_mma(
    const __nv_bfloat16* __restrict__ Ah, const __nv_bfloat16* __restrict__ Al,
    const __nv_bfloat16* __restrict__ Bh, const __nv_bfloat16* __restrict__ Bl,
    const float* __restrict__ bias, const float* __restrict__ res,
    float* __restrict__ C, int M, int N, int K)
{
    extern __shared__ char smem[];
    const uint32_t sbase = smem_u32(smem);

    const int tid = threadIdx.x;
    const int wid = tid >> 5, lane = tid & 31;
    const int bx = blockIdx.x, by = blockIdx.y;
    const int warp_m = wid & 1;        // 0..1 -> 64-row half
    const int warp_n = wid >> 1;       // 0..3 -> 32-col quarter

    float acc[4][4][4];
#pragma unroll
    for (int i = 0; i < 4; i++)
#pragma unroll
        for (int j = 0; j < 4; j++)
#pragma unroll
            for (int q = 0; q < 4; q++) acc[i][j][q] = 0.f;

    const int nchunk = K >> 6;

    // --- chunk loader: 4 tiles of 128x64 bf16 (16KB each) per stage ---
    auto load_chunk = [&](int ch, int s) {
        const int k0 = ch << 6;
        const uint32_t st = sbase + (uint32_t)s * 65536u;
#pragma unroll
        for (int it = 0; it < 4; it++) {
            const int idx = it * 256 + tid;
            const int row = idx >> 3, c = idx & 7;
            const uint32_t so = SWZ128((uint32_t)(row * 128 + c * 16));
            const size_t ga = (size_t)(by * 128 + row) * K + k0 + c * 8;
            const size_t gb = (size_t)(bx * 128 + row) * K + k0 + c * 8;
            cp_async16(st + so,          Ah + ga);
            cp_async16(st + 16384u + so, Al + ga);
            cp_async16(st + 32768u + so, Bh + gb);
            cp_async16(st + 49152u + so, Bl + gb);
        }
    };

    // --- chunk compute ---
    const int r8 = lane & 7, blk = lane >> 3;
    auto compute = [&](int s) {
        const uint32_t st = sbase + (uint32_t)s * 65536u;
        const uint32_t sa_h = st, sa_l = st + 16384u;
        const uint32_t sb_h = st + 32768u, sb_l = st + 49152u;
#pragma unroll
        for (int ks = 0; ks < 4; ks++) {
            const int kc = ks * 16;
            // B fragments: x4 covers 16n x 16k ->
            //   reg0=n0-7@k0, reg1=n0-7@k8, reg2=n8-15@k0, reg3=n8-15@k8
            uint32_t bh[2][4], bl[2][4];
#pragma unroll
            for (int nf = 0; nf < 2; nf++) {
                const int nrow = warp_n * 32 + nf * 16 + ((blk & 2) ? 8 : 0) + r8;
                const int kcol = kc + ((blk & 1) ? 8 : 0);
                const uint32_t off = SWZ128((uint32_t)(nrow * 128 + kcol * 2));
                ldsm_x4(bh[nf][0], bh[nf][1], bh[nf][2], bh[nf][3], sb_h + off);
                ldsm_x4(bl[nf][0], bl[nf][1], bl[nf][2], bl[nf][3], sb_l + off);
            }
#pragma unroll
            for (int mf = 0; mf < 4; mf++) {
                // A fragment: reg0=m0-7@k0, reg1=m8-15@k0, reg2=m0-7@k8, reg3=m8-15@k8
                const int mrow = warp_m * 64 + mf * 16 + ((blk & 1) ? 8 : 0) + r8;
                const int kcol = kc + ((blk & 2) ? 8 : 0);
                const uint32_t off = SWZ128((uint32_t)(mrow * 128 + kcol * 2));
                uint32_t ahf[4], alf[4];
                ldsm_x4(ahf[0], ahf[1], ahf[2], ahf[3], sa_h + off);
                ldsm_x4(alf[0], alf[1], alf[2], alf[3], sa_l + off);
#pragma unroll
                for (int nn = 0; nn < 4; nn++) {
                    const int g = nn >> 1, sb = nn & 1;
                    const uint32_t bhf[2] = {bh[g][sb * 2], bh[g][sb * 2 + 1]};
                    const uint32_t blf[2] = {bl[g][sb * 2], bl[g][sb * 2 + 1]};
                    mma16816(acc[mf][nn], ahf, bhf);   // Ah*Bh
                    mma16816(acc[mf][nn], ahf, blf);   // Ah*Bl
                    mma16816(acc[mf][nn], alf, bhf);   // Al*Bh
                }
            }
        }
    };

    // --- 2-stage pipeline ---
    load_chunk(0, 0);
    cp_commit();
    if (nchunk > 1) load_chunk(1, 1);
    cp_commit();
    cp_wait<1>();
    __syncthreads();

    for (int ch = 0; ch < nchunk; ch++) {
        compute(ch & 1);
        __syncthreads();                 // everyone done reading buf before refill
        if (ch + 2 < nchunk) load_chunk(ch + 2, ch & 1);
        cp_commit();
        cp_wait<1>();                    // next buffer ready
        __syncthreads();
    }

    // --- epilogue: d0,d1 = (m=T/4, n=2*(T%4)+{0,1}); d2,d3 = m+8 ---
    const int r4 = lane >> 2, c2 = (lane & 3) * 2;
#pragma unroll
    for (int mf = 0; mf < 4; mf++) {
#pragma unroll
        for (int nf = 0; nf < 4; nf++) {
#pragma unroll
            for (int hf = 0; hf < 2; hf++) {
                const int gr = by * 128 + warp_m * 64 + mf * 16 + r4 + hf * 8;
                const int gc = bx * 128 + warp_n * 32 + nf * 8 + c2;
                float2 v = {acc[mf][nf][hf * 2 + 0], acc[mf][nf][hf * 2 + 1]};
                const float2 bv = *(const float2*)(bias + gc);
                v.x += bv.x; v.y += bv.y;
                if (RELU) { v.x = fmaxf(v.x, 0.f); v.y = fmaxf(v.y, 0.f); }
                if (RES) {
                    const float2 rv = *(const float2*)(res + (size_t)gr * N + gc);
                    v.x += rv.x; v.y += rv.y;
                }
                *(float2*)(C + (size_t)gr * N + gc) = v;
            }
        }
    }
}

// ---------------------------------------------------------------------------
// Flash attention, fp32 (Round-5 target).
// ---------------------------------------------------------------------------
__global__ void __launch_bounds__(128) attn_kernel(
    const float* __restrict__ qkv, float* __restrict__ out)
{
    __shared__ float Ks[64][68];
    __shared__ float Vs[64][68];

    const int bid = blockIdx.x;
    const int qt = bid & 15;
    const int h  = (bid >> 4) & 15;
    const int n  = bid >> 8;
    const int tid = threadIdx.x;
    const int q_idx = qt * 128 + tid;

    const float* qrow = qkv + (size_t)(n * SEQ + q_idx) * D3 + h * 64;
    float q[64];
#pragma unroll
    for (int d = 0; d < 64; d += 4) {
        const float4 v = *(const float4*)(qrow + d);
        q[d + 0] = v.x * 0.125f; q[d + 1] = v.y * 0.125f;
        q[d + 2] = v.z * 0.125f; q[d + 3] = v.w * 0.125f;
    }

    float m = -1e30f, l = 0.f;
    float o[64];
#pragma unroll
    for (int d = 0; d < 64; d++) o[d] = 0.f;

    const int jl = tid >> 1;
    const int dl = (tid & 1) * 32;

    for (int kt = 0; kt < 32; kt++) {
        __syncthreads();
        const float* kbase = qkv + (size_t)(n * SEQ + kt * 64 + jl) * D3
                             + DMODEL + h * 64 + dl;
        const float* vbase = kbase + DMODEL;
#pragma unroll
        for (int rr = 0; rr < 8; rr++) {
            *(float4*)&Ks[jl][dl + rr * 4] = *(const float4*)(kbase + rr * 4);
            *(float4*)&Vs[jl][dl + rr * 4] = *(const float4*)(vbase + rr * 4);
        }
        __syncthreads();

        for (int j = 0; j < 64; j++) {
            float s = 0.f;
#pragma unroll
            for (int d = 0; d < 64; d += 4) {
                const float4 kv = *(const float4*)&Ks[j][d];
                s = fmaf(q[d + 0], kv.x, s);
                s = fmaf(q[d + 1], kv.y, s);
                s = fmaf(q[d + 2], kv.z, s);
                s = fmaf(q[d + 3], kv.w, s);
            }
            if (s > m) {
                const float c = __expf(m - s);
                l *= c;
#pragma unroll
                for (int d = 0; d < 64; d++) o[d] *= c;
                m = s;
            }
            const float p = __expf(s - m);
            l += p;
#pragma unroll
            for (int d = 0; d < 64; d += 4) {
                const float4 vv = *(const float4*)&Vs[j][d];
                o[d + 0] = fmaf(p, vv.x, o[d + 0]);
                o[d + 1] = fmaf(p, vv.y, o[d + 1]);
                o[d + 2] = fmaf(p, vv.z, o[d + 2]);
                o[d + 3] = fmaf(p, vv.w, o[d + 3]);
            }
        }
    }

    const float inv = 1.f / l;
    float* op = out + (size_t)(n * SEQ + q_idx) * DMODEL + h * 64;
#pragma unroll
    for (int d = 0; d < 64; d += 4) {
        float4 v;
        v.x = o[d + 0] * inv; v.y = o[d + 1] * inv;
        v.z = o[d + 2] * inv; v.w = o[d + 3] * inv;
        *(float4*)(op + d) = v;
    }
}

// ---------------------------------------------------------------------------
// LayerNorm over last dim (1024). One block per row, 256 threads x float4.
// ---------------------------------------------------------------------------
__global__ void __launch_bounds__(256) ln_kernel(
    const float* __restrict__ in, const float* __restrict__ gamma,
    const float* __restrict__ beta, float* __restrict__ out)
{
    const int row = blockIdx.x;
    const int tid = threadIdx.x;
    const float4 v = ((const float4*)(in + (size_t)row * DMODEL))[tid];

    float s  = v.x + v.y + v.z + v.w;
    float sq = v.x * v.x + v.y * v.y + v.z * v.z + v.w * v.w;
#pragma unroll
    for (int off = 16; off > 0; off >>= 1) {
        s  += __shfl_xor_sync(0xffffffffu, s,  off);
        sq += __shfl_xor_sync(0xffffffffu, sq, off);
    }
    __shared__ float ss[8], qq[8];
    if ((tid & 31) == 0) { ss[tid >> 5] = s; qq[tid >> 5] = sq; }
    __syncthreads();
    float tot = 0.f, totq = 0.f;
#pragma unroll
    for (int i = 0; i < 8; i++) { tot += ss[i]; totq += qq[i]; }

    const float mu  = tot * (1.f / DMODEL);
    const float var = totq * (1.f / DMODEL) - mu * mu;
    const float rs  = rsqrtf(var + 1e-5f);

    const float4 g = ((const float4*)gamma)[tid];
    const float4 b = ((const float4*)beta)[tid];
    float4 o;
    o.x = (v.x - mu) * rs * g.x + b.x;
    o.y = (v.y - mu) * rs * g.y + b.y;
    o.z = (v.z - mu) * rs * g.z + b.z;
    o.w = (v.w - mu) * rs * g.w + b.w;
    ((float4*)(out + (size_t)row * DMODEL))[tid] = o;
}

// ---------------------------------------------------------------------------
extern "C" void kernel_launch(void* const* d_in, const int* in_sizes, int n_in,
                              void* d_out, int out_size)
{
    (void)in_sizes; (void)n_in; (void)out_size;
    const float* x     = (const float*)d_in[0];
    const float* w_qkv = (const float*)d_in[1];
    const float* b_qkv = (const float*)d_in[2];
    const float* w_o   = (const float*)d_in[3];
    const float* b_o   = (const float*)d_in[4];
    const float* g1    = (const float*)d_in[5];
    const float* be1   = (const float*)d_in[6];
    const float* w1    = (const float*)d_in[7];
    const float* b1    = (const float*)d_in[8];
    const float* w2    = (const float*)d_in[9];
    const float* b2    = (const float*)d_in[10];
    const float* g2    = (const float*)d_in[11];
    const float* be2   = (const float*)d_in[12];
    float* out = (float*)d_out;

    float *qkv, *attn, *res, *h, *ff;
    __nv_bfloat16 *a_hi, *a_lo, *w_hi, *w_lo;
    cudaGetSymbolAddress((void**)&qkv,  g_qkv);
    cudaGetSymbolAddress((void**)&attn, g_attn);
    cudaGetSymbolAddress((void**)&res,  g_res);
    cudaGetSymbolAddress((void**)&h,    g_h);
    cudaGetSymbolAddress((void**)&ff,   g_ff);
    cudaGetSymbolAddress((void**)&a_hi, g_a_hi);
    cudaGetSymbolAddress((void**)&a_lo, g_a_lo);
    cudaGetSymbolAddress((void**)&w_hi, g_w_hi);
    cudaGetSymbolAddress((void**)&w_lo, g_w_lo);

    cudaFuncSetAttribute(gemm_mma<false, false>,
        cudaFuncAttributeMaxDynamicSharedMemorySize, GEMM_SMEM_BYTES);
    cudaFuncSetAttribute(gemm_mma<false, true>,
        cudaFuncAttributeMaxDynamicSharedMemorySize, GEMM_SMEM_BYTES);
    cudaFuncSetAttribute(gemm_mma<true, false>,
        cudaFuncAttributeMaxDynamicSharedMemorySize, GEMM_SMEM_BYTES);

    const dim3 tsb(32, 8);

    // 1) qkv = x @ w_qkv + b_qkv
    split_kernel<<<(T_TOK * DMODEL / 4 + 255) / 256, 256>>>(x, a_hi, a_lo,
                                                            T_TOK * DMODEL / 4);
    tsplit_kernel<<<dim3(D3 / 32, DMODEL / 32), tsb>>>(w_qkv, w_hi, w_lo,
                                                       DMODEL, D3);
    gemm_mma<false, false><<<dim3(D3 / 128, T_TOK / 128), 256, GEMM_SMEM_BYTES>>>(
        a_hi, a_lo, w_hi, w_lo, b_qkv, nullptr, qkv, T_TOK, D3, DMODEL);

    // 2) attention (fp32)
    attn_kernel<<<512, 128>>>(qkv, attn);

    // 3) res1 = attn @ w_o + b_o + x
    split_kernel<<<(T_TOK * DMODEL / 4 + 255) / 256, 256>>>(attn, a_hi, a_lo,
                                                            T_TOK * DMODEL / 4);
    tsplit_kernel<<<dim3(DMODEL / 32, DMODEL / 32), tsb>>>(w_o, w_hi, w_lo,
                                                           DMODEL, DMODEL);
    gemm_mma<false, true><<<dim3(DMODEL / 128, T_TOK / 128), 256, GEMM_SMEM_BYTES>>>(
        a_hi, a_lo, w_hi, w_lo, b_o, x, res, T_TOK, DMODEL, DMODEL);

    // 4) h = LN(res1)
    ln_kernel<<<T_TOK, 256>>>(res, g1, be1, h);

    // 5) ff = relu(h @ w1 + b1)
    split_kernel<<<(T_TOK * DMODEL / 4 + 255) / 256, 256>>>(h, a_hi, a_lo,
                                                            T_TOK * DMODEL / 4);
    tsplit_kernel<<<dim3(FFDIM / 32, DMODEL / 32), tsb>>>(w1, w_hi, w_lo,
                                                          DMODEL, FFDIM);
    gemm_mma<true, false><<<dim3(FFDIM / 128, T_TOK / 128), 256, GEMM_SMEM_BYTES>>>(
        a_hi, a_lo, w_hi, w_lo, b1, nullptr, ff, T_TOK, FFDIM, DMODEL);

    // 6) res2 = ff @ w2 + b2 + h
    split_kernel<<<(T_TOK * FFDIM / 4 + 255) / 256, 256>>>(ff, a_hi, a_lo,
                                                           T_TOK * FFDIM / 4);
    tsplit_kernel<<<dim3(DMODEL / 32, FFDIM / 32), tsb>>>(w2, w_hi, w_lo,
                                                          FFDIM, DMODEL);
    gemm_mma<false, true><<<dim3(DMODEL / 128, T_TOK / 128), 256, GEMM_SMEM_BYTES>>>(
        a_hi, a_lo, w_hi, w_lo, b2, h, res, T_TOK, DMODEL, FFDIM);

    // 7) out = LN(res2)
    ln_kernel<<<T_TOK, 256>>>(res, g2, be2, out);
}

// round 6
// speedup vs baseline: 3.5331x; 2.0845x over previous
#include <cuda_runtime.h>
#include <cuda_bf16.h>
#include <math.h>
#include <stdint.h>

// ---------------------------------------------------------------------------
// Encoder layer: N=2, L=2048, D=1024, H=16, HD=64, FF=4096, fp32 in/out.
// GEMMs + attention on mma.sync bf16 split-3 (baseline-ISA HMMA).
// ---------------------------------------------------------------------------

#define T_TOK 4096
#define DMODEL 1024
#define D3 3072
#define FFDIM 4096
#define SEQ 2048

// Scratch (allocation-free: __device__ globals)
__device__ float g_qkv [T_TOK * (size_t)D3];     // reused as bf16 hi/lo qkv
__device__ float g_attn[T_TOK * (size_t)DMODEL]; // reused as bf16 hi/lo attn-out
__device__ float g_res [T_TOK * (size_t)DMODEL];
__device__ float g_h   [T_TOK * (size_t)DMODEL];
__device__ float g_ff  [T_TOK * (size_t)FFDIM];  // reused as bf16 hi/lo ff
__device__ __nv_bfloat16 g_a_hi[T_TOK * (size_t)FFDIM];
__device__ __nv_bfloat16 g_a_lo[T_TOK * (size_t)FFDIM];
__device__ __nv_bfloat16 g_w_hi[(size_t)FFDIM * DMODEL];
__device__ __nv_bfloat16 g_w_lo[(size_t)FFDIM * DMODEL];

// ---------------------------------------------------------------------------
// Baseline-ISA PTX helpers
// ---------------------------------------------------------------------------
__device__ __forceinline__ uint32_t smem_u32(const void* p) {
    uint32_t a;
    asm("{ .reg .u64 t; cvta.to.shared.u64 t, %1; cvt.u32.u64 %0, t; }"
        : "=r"(a) : "l"(p));
    return a;
}
__device__ __forceinline__ void ldsm_x4(uint32_t& r0, uint32_t& r1,
                                        uint32_t& r2, uint32_t& r3,
                                        uint32_t addr) {
    asm volatile("ldmatrix.sync.aligned.m8n8.x4.shared.b16 {%0,%1,%2,%3}, [%4];"
                 : "=r"(r0), "=r"(r1), "=r"(r2), "=r"(r3) : "r"(addr));
}
__device__ __forceinline__ void ldsm_x4_t(uint32_t& r0, uint32_t& r1,
                                          uint32_t& r2, uint32_t& r3,
                                          uint32_t addr) {
    asm volatile(
        "ldmatrix.sync.aligned.m8n8.x4.trans.shared.b16 {%0,%1,%2,%3}, [%4];"
        : "=r"(r0), "=r"(r1), "=r"(r2), "=r"(r3) : "r"(addr));
}
__device__ __forceinline__ void mma16816(float* d, const uint32_t* a,
                                         const uint32_t* b) {
    asm volatile(
        "mma.sync.aligned.m16n8k16.row.col.f32.bf16.bf16.f32 "
        "{%0,%1,%2,%3}, {%4,%5,%6,%7}, {%8,%9}, {%0,%1,%2,%3};"
        : "+f"(d[0]), "+f"(d[1]), "+f"(d[2]), "+f"(d[3])
        : "r"(a[0]), "r"(a[1]), "r"(a[2]), "r"(a[3]), "r"(b[0]), "r"(b[1]));
}
__device__ __forceinline__ void cp_async16(uint32_t dst, const void* src) {
    asm volatile("cp.async.cg.shared.global [%0], [%1], 16;"
                 :: "r"(dst), "l"(src));
}
__device__ __forceinline__ void cp_commit() {
    asm volatile("cp.async.commit_group;" ::: "memory");
}
template<int W> __device__ __forceinline__ void cp_wait() {
    asm volatile("cp.async.wait_group %0;" :: "n"(W) : "memory");
}
// pack two fp32 -> bf16x2 (a -> low half, b -> high half)
__device__ __forceinline__ uint32_t pack2bf(float a, float b) {
    uint32_t r;
    asm("cvt.rn.bf16x2.f32 %0, %1, %2;" : "=r"(r) : "f"(b), "f"(a));
    return r;
}
__device__ __forceinline__ float lowf(uint32_t u) {
    return __uint_as_float(u << 16);
}
__device__ __forceinline__ float highf(uint32_t u) {
    return __uint_as_float(u & 0xFFFF0000u);
}
// fast 2^x on the FMA pipe (x <= 0 expected), rel err ~2e-6
__device__ __forceinline__ float fexp2(float x) {
    x = fmaxf(x, -120.f);
    const int ei = __float2int_rn(x);
    const float f = x - (float)ei;
    float p = 1.3333558e-3f;
    p = fmaf(p, f, 9.6181291e-3f);
    p = fmaf(p, f, 5.5504109e-2f);
    p = fmaf(p, f, 2.4022651e-1f);
    p = fmaf(p, f, 6.9314718e-1f);
    p = fmaf(p, f, 1.0f);
    return p * __int_as_float((ei + 127) << 23);
}

#define SWZ128(o) ((o) ^ (((o) >> 3) & 0x70))

// ---------------------------------------------------------------------------
// fp32 -> bf16 hi/lo split (row-major passthrough) — used for x only
// ---------------------------------------------------------------------------
__global__ void __launch_bounds__(256) split_kernel(
    const float* __restrict__ in, __nv_bfloat16* __restrict__ hi,
    __nv_bfloat16* __restrict__ lo, int n4)
{
    int i = blockIdx.x * 256 + threadIdx.x;
    if (i >= n4) return;
    const float4 v = ((const float4*)in)[i];
    const uint32_t h0 = pack2bf(v.x, v.y), h1 = pack2bf(v.z, v.w);
    const uint32_t l0 = pack2bf(v.x - lowf(h0), v.y - highf(h0));
    const uint32_t l1 = pack2bf(v.z - lowf(h1), v.w - highf(h1));
    ((uint2*)hi)[i] = make_uint2(h0, h1);
    ((uint2*)lo)[i] = make_uint2(l0, l1);
}

// ---------------------------------------------------------------------------
// Weight transpose + split: in [Kd, Nd] fp32 -> hi/lo [Nd, Kd] bf16
// ---------------------------------------------------------------------------
__global__ void __launch_bounds__(256) tsplit_kernel(
    const float* __restrict__ in, __nv_bfloat16* __restrict__ hi,
    __nv_bfloat16* __restrict__ lo, int Kd, int Nd)
{
    __shared__ float t[32][33];
    const int n0 = blockIdx.x * 32, k0 = blockIdx.y * 32;
    const int tx = threadIdx.x, ty = threadIdx.y;
#pragma unroll
    for (int r = 0; r < 32; r += 8)
        t[ty + r][tx] = in[(size_t)(k0 + ty + r) * Nd + n0 + tx];
    __syncthreads();
#pragma unroll
    for (int r = 0; r < 32; r += 8) {
        const float v = t[tx][ty + r];
        const __nv_bfloat16 h = __float2bfloat16(v);
        const __nv_bfloat16 l = __float2bfloat16(v - __bfloat162float(h));
        const size_t o = (size_t)(n0 + ty + r) * Kd + k0 + tx;
        hi[o] = h;
        lo[o] = l;
    }
}

// ---------------------------------------------------------------------------
// bf16 split-3 GEMM via mma.sync. OSPLIT: write bf16 hi/lo instead of fp32.
// ---------------------------------------------------------------------------
#define GEMM_SMEM_BYTES (2 * 65536)

template<bool RELU, bool RES, bool OSPLIT>
__global__ void __launch_bounds__(256, 1) gemm_mma(
    const __nv_bfloat16* __restrict__ Ah, const __nv_bfloat16* __restrict__ Al,
    const __nv_bfloat16* __restrict__ Bh, const __nv_bfloat16* __restrict__ Bl,
    const float* __restrict__ bias, const float* __restrict__ res,
    float* __restrict__ C, __nv_bfloat16* __restrict__ Chi,
    __nv_bfloat16* __restrict__ Clo, int M, int N, int K)
{
    extern __shared__ char smem[];
    const uint32_t sbase = smem_u32(smem);

    const int tid = threadIdx.x;
    const int wid = tid >> 5, lane = tid & 31;
    const int bx = blockIdx.x, by = blockIdx.y;
    const int warp_m = wid & 1;
    const int warp_n = wid >> 1;

    float acc[4][4][4];
#pragma unroll
    for (int i = 0; i < 4; i++)
#pragma unroll
        for (int j = 0; j < 4; j++)
#pragma unroll
            for (int q = 0; q < 4; q++) acc[i][j][q] = 0.f;

    const int nchunk = K >> 6;

    auto load_chunk = [&](int ch, int s) {
        const int k0 = ch << 6;
        const uint32_t st = sbase + (uint32_t)s * 65536u;
#pragma unroll
        for (int it = 0; it < 4; it++) {
            const int idx = it * 256 + tid;
            const int row = idx >> 3, c = idx & 7;
            const uint32_t so = SWZ128((uint32_t)(row * 128 + c * 16));
            const size_t ga = (size_t)(by * 128 + row) * K + k0 + c * 8;
            const size_t gb = (size_t)(bx * 128 + row) * K + k0 + c * 8;
            cp_async16(st + so,          Ah + ga);
            cp_async16(st + 16384u + so, Al + ga);
            cp_async16(st + 32768u + so, Bh + gb);
            cp_async16(st + 49152u + so, Bl + gb);
        }
    };

    const int r8 = lane & 7, blk = lane >> 3;
    auto compute = [&](int s) {
        const uint32_t st = sbase + (uint32_t)s * 65536u;
        const uint32_t sa_h = st, sa_l = st + 16384u;
        const uint32_t sb_h = st + 32768u, sb_l = st + 49152u;
#pragma unroll
        for (int ks = 0; ks < 4; ks++) {
            const int kc = ks * 16;
            uint32_t bh[2][4], bl[2][4];
#pragma unroll
            for (int nf = 0; nf < 2; nf++) {
                const int nrow = warp_n * 32 + nf * 16 + ((blk & 2) ? 8 : 0) + r8;
                const int kcol = kc + ((blk & 1) ? 8 : 0);
                const uint32_t off = SWZ128((uint32_t)(nrow * 128 + kcol * 2));
                ldsm_x4(bh[nf][0], bh[nf][1], bh[nf][2], bh[nf][3], sb_h + off);
                ldsm_x4(bl[nf][0], bl[nf][1], bl[nf][2], bl[nf][3], sb_l + off);
            }
#pragma unroll
            for (int mf = 0; mf < 4; mf++) {
                const int mrow = warp_m * 64 + mf * 16 + ((blk & 1) ? 8 : 0) + r8;
                const int kcol = kc + ((blk & 2) ? 8 : 0);
                const uint32_t off = SWZ128((uint32_t)(mrow * 128 + kcol * 2));
                uint32_t ahf[4], alf[4];
                ldsm_x4(ahf[0], ahf[1], ahf[2], ahf[3], sa_h + off);
                ldsm_x4(alf[0], alf[1], alf[2], alf[3], sa_l + off);
#pragma unroll
                for (int nn = 0; nn < 4; nn++) {
                    const int g = nn >> 1, sb = nn & 1;
                    const uint32_t bhf[2] = {bh[g][sb * 2], bh[g][sb * 2 + 1]};
                    const uint32_t blf[2] = {bl[g][sb * 2], bl[g][sb * 2 + 1]};
                    mma16816(acc[mf][nn], ahf, bhf);
                    mma16816(acc[mf][nn], ahf, blf);
                    mma16816(acc[mf][nn], alf, bhf);
                }
            }
        }
    };

    load_chunk(0, 0);
    cp_commit();
    if (nchunk > 1) load_chunk(1, 1);
    cp_commit();
    cp_wait<1>();
    __syncthreads();

    for (int ch = 0; ch < nchunk; ch++) {
        compute(ch & 1);
        __syncthreads();
        if (ch + 2 < nchunk) load_chunk(ch + 2, ch & 1);
        cp_commit();
        cp_wait<1>();
        __syncthreads();
    }

    const int r4 = lane >> 2, c2 = (lane & 3) * 2;
#pragma unroll
    for (int mf = 0; mf < 4; mf++) {
#pragma unroll
        for (int nf = 0; nf < 4; nf++) {
#pragma unroll
            for (int hf = 0; hf < 2; hf++) {
                const int gr = by * 128 + warp_m * 64 + mf * 16 + r4 + hf * 8;
                const int gc = bx * 128 + warp_n * 32 + nf * 8 + c2;
                float2 v = {acc[mf][nf][hf * 2 + 0], acc[mf][nf][hf * 2 + 1]};
                const float2 bv = *(const float2*)(bias + gc);
                v.x += bv.x; v.y += bv.y;
                if (RELU) { v.x = fmaxf(v.x, 0.f); v.y = fmaxf(v.y, 0.f); }
                if (RES) {
                    const float2 rv = *(const float2*)(res + (size_t)gr * N + gc);
                    v.x += rv.x; v.y += rv.y;
                }
                if (OSPLIT) {
                    const uint32_t hv = pack2bf(v.x, v.y);
                    const uint32_t lv = pack2bf(v.x - lowf(hv), v.y - highf(hv));
                    *(uint32_t*)&Chi[(size_t)gr * N + gc] = hv;
                    *(uint32_t*)&Clo[(size_t)gr * N + gc] = lv;
                } else {
                    *(float2*)(C + (size_t)gr * N + gc) = v;
                }
            }
        }
    }
}

// ---------------------------------------------------------------------------
// Flash attention on mma.sync, bf16 split-3 scores and P*V, fp32 softmax.
// CTA = (batch, head, 128 queries); 8 warps x 16 query rows; key tiles of 64,
// double-buffered cp.async. Emits bf16 hi/lo output splits directly.
// ---------------------------------------------------------------------------
#define ATT_SMEM 110592   // Q hi/lo 2*18432 + 2 stages * 4 arrays * 9216

__global__ void __launch_bounds__(256) attn_mma(
    const __nv_bfloat16* __restrict__ gqh, const __nv_bfloat16* __restrict__ gql,
    __nv_bfloat16* __restrict__ goh, __nv_bfloat16* __restrict__ gol)
{
    extern __shared__ char smem[];
    const uint32_t sQ  = smem_u32(smem);       // Qh[128][72], Ql[128][72]
    const uint32_t sKV = sQ + 36864u;          // per stage: Kh,Kl,Vh,Vl [64][72]

    const int tid = threadIdx.x, wid = tid >> 5, lane = tid & 31;
    const int qt = blockIdx.x & 15;
    const int h  = (blockIdx.x >> 4) & 15;
    const int n  = blockIdx.x >> 8;
    const size_t tokQ = (size_t)n * SEQ + qt * 128;

    // Q tile load (hi/lo), 128 rows x 128B, padded rows of 144B
#pragma unroll
    for (int it = 0; it < 8; it++) {
        const int idx = it * 256 + tid;
        const int arr = idx >> 10, rem = idx & 1023;
        const int row = rem >> 3, c = rem & 7;
        const __nv_bfloat16* s = (arr ? gql : gqh)
            + (tokQ + row) * D3 + h * 64 + c * 8;
        cp_async16(sQ + (uint32_t)arr * 18432u + (uint32_t)row * 144u
                   + (uint32_t)c * 16u, s);
    }
    auto load_kv = [&](int kt, int st) {
        const uint32_t sb = sKV + (uint32_t)st * 36864u;
        const size_t tokK = (size_t)n * SEQ + kt * 64;
#pragma unroll
        for (int it = 0; it < 8; it++) {
            const int idx = it * 256 + tid;
            const int arr = idx >> 9, rem = idx & 511;    // 0 Kh,1 Kl,2 Vh,3 Vl
            const int row = rem >> 3, c = rem & 7;
            const __nv_bfloat16* s = ((arr & 1) ? gql : gqh)
                + (tokK + row) * D3 + ((arr >> 1) ? 2048 : 1024) + h * 64 + c * 8;
            cp_async16(sb + (uint32_t)arr * 9216u + (uint32_t)row * 144u
                       + (uint32_t)c * 16u, s);
        }
    };

    load_kv(0, 0); cp_commit();
    load_kv(1, 1); cp_commit();
    cp_wait<1>();
    __syncthreads();

    float m0 = -1e30f, m1 = -1e30f, l0 = 0.f, l1 = 0.f;
    float oacc[8][4];
#pragma unroll
    for (int i = 0; i < 8; i++)
#pragma unroll
        for (int j = 0; j < 4; j++) oacc[i][j] = 0.f;

    const int r8 = lane & 7, blk = lane >> 3;
    // A-frag addressing (Q and trans-V): row +8 for lanes 8-15/24-31, col +8 for 16-31
    const int arow = ((blk & 1) ? 8 : 0) + r8;
    const int acol = ((blk & 2) ? 8 : 0);
    // B-frag addressing (K): row +8 for lanes 16-31, col +8 for 8-15/24-31
    const int brow = ((blk & 2) ? 8 : 0) + r8;
    const int bcol = ((blk & 1) ? 8 : 0);
    const uint32_t qro = (uint32_t)(wid * 16 + arow) * 144u;
    const float ksc = 0.18033688011112042f;   // 1/8 * log2(e)

    for (int kt = 0; kt < 32; kt++) {
        const uint32_t sb  = sKV + (uint32_t)(kt & 1) * 36864u;
        const uint32_t sKh = sb, sKl = sb + 9216u;
        const uint32_t sVh = sb + 18432u, sVl = sb + 27648u;

        // ---- S = Q K^T (split-3) ----
        float sacc[8][4];
#pragma unroll
        for (int i = 0; i < 8; i++)
#pragma unroll
            for (int j = 0; j < 4; j++) sacc[i][j] = 0.f;

#pragma unroll
        for (int kf = 0; kf < 4; kf++) {
            const uint32_t qo = qro + (uint32_t)(kf * 16 + acol) * 2u;
            uint32_t qhf[4], qlf[4];
            ldsm_x4(qhf[0], qhf[1], qhf[2], qhf[3], sQ + qo);
            ldsm_x4(qlf[0], qlf[1], qlf[2], qlf[3], sQ + 18432u + qo);
            const uint32_t kc = (uint32_t)(kf * 16 + bcol) * 2u;
#pragma unroll
            for (int np = 0; np < 4; np++) {
                const uint32_t ko = (uint32_t)(np * 16 + brow) * 144u + kc;
                uint32_t kh[4], kl[4];
                ldsm_x4(kh[0], kh[1], kh[2], kh[3], sKh + ko);
                ldsm_x4(kl[0], kl[1], kl[2], kl[3], sKl + ko);
#pragma unroll
                for (int s2 = 0; s2 < 2; s2++) {
                    const uint32_t bh[2] = {kh[s2 * 2], kh[s2 * 2 + 1]};
                    const uint32_t bl[2] = {kl[s2 * 2], kl[s2 * 2 + 1]};
                    float* a = sacc[np * 2 + s2];
                    mma16816(a, qhf, bh);
                    mma16816(a, qhf, bl);
                    mma16816(a, qlf, bh);
                }
            }
        }

        // ---- online softmax (base-2, fast exp on FMA pipe) ----
        float mx0 = -1e30f, mx1 = -1e30f;
#pragma unroll
        for (int nn = 0; nn < 8; nn++) {
            mx0 = fmaxf(mx0, fmaxf(sacc[nn][0], sacc[nn][1]));
            mx1 = fmaxf(mx1, fmaxf(sacc[nn][2], sacc[nn][3]));
        }
        mx0 *= ksc; mx1 *= ksc;
        mx0 = fmaxf(mx0, __shfl_xor_sync(0xffffffffu, mx0, 1));
        mx0 = fmaxf(mx0, __shfl_xor_sync(0xffffffffu, mx0, 2));
        mx1 = fmaxf(mx1, __shfl_xor_sync(0xffffffffu, mx1, 1));
        mx1 = fmaxf(mx1, __shfl_xor_sync(0xffffffffu, mx1, 2));
        const float mn0 = fmaxf(m0, mx0), mn1 = fmaxf(m1, mx1);
        const float c0 = fexp2(m0 - mn0), c1 = fexp2(m1 - mn1);
        m0 = mn0; m1 = mn1;

        float sum0 = 0.f, sum1 = 0.f;
        uint32_t phi[4][4], plo[4][4];
#pragma unroll
        for (int nn = 0; nn < 8; nn++) {
            const float p0 = fexp2(fmaf(sacc[nn][0], ksc, -mn0));
            const float p1 = fexp2(fmaf(sacc[nn][1], ksc, -mn0));
            const float p2 = fexp2(fmaf(sacc[nn][2], ksc, -mn1));
            const float p3 = fexp2(fmaf(sacc[nn][3], ksc, -mn1));
            sum0 += p0 + p1; sum1 += p2 + p3;
            const uint32_t h01 = pack2bf(p0, p1), h23 = pack2bf(p2, p3);
            const uint32_t l01 = pack2bf(p0 - lowf(h01), p1 - highf(h01));
            const uint32_t l23 = pack2bf(p2 - lowf(h23), p3 - highf(h23));
            const int j = nn >> 1, o = (nn & 1) * 2;
            phi[j][o] = h01; phi[j][o + 1] = h23;
            plo[j][o] = l01; plo[j][o + 1] = l23;
        }
        sum0 += __shfl_xor_sync(0xffffffffu, sum0, 1);
        sum0 += __shfl_xor_sync(0xffffffffu, sum0, 2);
        sum1 += __shfl_xor_sync(0xffffffffu, sum1, 1);
        sum1 += __shfl_xor_sync(0xffffffffu, sum1, 2);
        l0 = fmaf(l0, c0, sum0);
        l1 = fmaf(l1, c1, sum1);
#pragma unroll
        for (int nn = 0; nn < 8; nn++) {
            oacc[nn][0] *= c0; oacc[nn][1] *= c0;
            oacc[nn][2] *= c1; oacc[nn][3] *= c1;
        }

        // ---- O += P V (split-3), V^T via ldmatrix.trans ----
#pragma unroll
        for (int j = 0; j < 4; j++) {
            const uint32_t vr = (uint32_t)(j * 16 + arow) * 144u;
#pragma unroll
            for (int dp = 0; dp < 4; dp++) {
                const uint32_t vo = vr + (uint32_t)(dp * 16 + acol) * 2u;
                uint32_t vh[4], vl[4];
                ldsm_x4_t(vh[0], vh[1], vh[2], vh[3], sVh + vo);
                ldsm_x4_t(vl[0], vl[1], vl[2], vl[3], sVl + vo);
#pragma unroll
                for (int s2 = 0; s2 < 2; s2++) {
                    const uint32_t bh[2] = {vh[s2 * 2], vh[s2 * 2 + 1]};
                    const uint32_t bl[2] = {vl[s2 * 2], vl[s2 * 2 + 1]};
                    float* a = oacc[dp * 2 + s2];
                    mma16816(a, phi[j], bh);
                    mma16816(a, phi[j], bl);
                    mma16816(a, plo[j], bh);
                }
            }
        }

        __syncthreads();
        if (kt + 2 < 32) load_kv(kt + 2, kt & 1);
        cp_commit();
        cp_wait<1>();
        __syncthreads();
    }

    // ---- finalize + write bf16 hi/lo splits ----
    const float il0 = 1.f / l0, il1 = 1.f / l1;
    const int r4 = lane >> 2, c2 = (lane & 3) * 2;
    const size_t row0 = (tokQ + wid * 16 + r4) * DMODEL + h * 64;
    const size_t row1 = row0 + 8 * DMODEL;
#pragma unroll
    for (int nn = 0; nn < 8; nn++) {
        const int col = nn * 8 + c2;
        const float f0 = oacc[nn][0] * il0, f1 = oacc[nn][1] * il0;
        const float f2 = oacc[nn][2] * il1, f3 = oacc[nn][3] * il1;
        const uint32_t h01 = pack2bf(f0, f1), h23 = pack2bf(f2, f3);
        *(uint32_t*)&goh[row0 + col] = h01;
        *(uint32_t*)&goh[row1 + col] = h23;
        *(uint32_t*)&gol[row0 + col] = pack2bf(f0 - lowf(h01), f1 - highf(h01));
        *(uint32_t*)&gol[row1 + col] = pack2bf(f2 - lowf(h23), f3 - highf(h23));
    }
}

// ---------------------------------------------------------------------------
// LayerNorm over last dim (1024). Optionally emits bf16 hi/lo split.
// ---------------------------------------------------------------------------
template<bool SPLIT>
__global__ void __launch_bounds__(256) ln_kernel(
    const float* __restrict__ in, const float* __restrict__ gamma,
    const float* __restrict__ beta, float* __restrict__ out,
    __nv_bfloat16* __restrict__ hi, __nv_bfloat16* __restrict__ lo)
{
    const int row = blockIdx.x;
    const int tid = threadIdx.x;
    const float4 v = ((const float4*)(in + (size_t)row * DMODEL))[tid];

    float s  = v.x + v.y + v.z + v.w;
    float sq = v.x * v.x + v.y * v.y + v.z * v.z + v.w * v.w;
#pragma unroll
    for (int off = 16; off > 0; off >>= 1) {
        s  += __shfl_xor_sync(0xffffffffu, s,  off);
        sq += __shfl_xor_sync(0xffffffffu, sq, off);
    }
    __shared__ float ss[8], qq[8];
    if ((tid & 31) == 0) { ss[tid >> 5] = s; qq[tid >> 5] = sq; }
    __syncthreads();
    float tot = 0.f, totq = 0.f;
#pragma unroll
    for (int i = 0; i < 8; i++) { tot += ss[i]; totq += qq[i]; }

    const float mu  = tot * (1.f / DMODEL);
    const float var = totq * (1.f / DMODEL) - mu * mu;
    const float rs  = rsqrtf(var + 1e-5f);

    const float4 g = ((const float4*)gamma)[tid];
    const float4 b = ((const float4*)beta)[tid];
    float4 o;
    o.x = (v.x - mu) * rs * g.x + b.x;
    o.y = (v.y - mu) * rs * g.y + b.y;
    o.z = (v.z - mu) * rs * g.z + b.z;
    o.w = (v.w - mu) * rs * g.w + b.w;
    ((float4*)(out + (size_t)row * DMODEL))[tid] = o;
    if (SPLIT) {
        const uint32_t h0 = pack2bf(o.x, o.y), h1 = pack2bf(o.z, o.w);
        const uint32_t l0 = pack2bf(o.x - lowf(h0), o.y - highf(h0));
        const uint32_t l1 = pack2bf(o.z - lowf(h1), o.w - highf(h1));
        *(uint2*)&hi[(size_t)row * DMODEL + tid * 4] = make_uint2(h0, h1);
        *(uint2*)&lo[(size_t)row * DMODEL + tid * 4] = make_uint2(l0, l1);
    }
}

// ---------------------------------------------------------------------------
extern "C" void kernel_launch(void* const* d_in, const int* in_sizes, int n_in,
                              void* d_out, int out_size)
{
    (void)in_sizes; (void)n_in; (void)out_size;
    const float* x     = (const float*)d_in[0];
    const float* w_qkv = (const float*)d_in[1];
    const float* b_qkv = (const float*)d_in[2];
    const float* w_o   = (const float*)d_in[3];
    const float* b_o   = (const float*)d_in[4];
    const float* g1    = (const float*)d_in[5];
    const float* be1   = (const float*)d_in[6];
    const float* w1    = (const float*)d_in[7];
    const float* b1    = (const float*)d_in[8];
    const float* w2    = (const float*)d_in[9];
    const float* b2    = (const float*)d_in[10];
    const float* g2    = (const float*)d_in[11];
    const float* be2   = (const float*)d_in[12];
    float* out = (float*)d_out;

    float *qkv, *attn, *res, *h, *ff;
    __nv_bfloat16 *a_hi, *a_lo, *w_hi, *w_lo;
    cudaGetSymbolAddress((void**)&qkv,  g_qkv);
    cudaGetSymbolAddress((void**)&attn, g_attn);
    cudaGetSymbolAddress((void**)&res,  g_res);
    cudaGetSymbolAddress((void**)&h,    g_h);
    cudaGetSymbolAddress((void**)&ff,   g_ff);
    cudaGetSymbolAddress((void**)&a_hi, g_a_hi);
    cudaGetSymbolAddress((void**)&a_lo, g_a_lo);
    cudaGetSymbolAddress((void**)&w_hi, g_w_hi);
    cudaGetSymbolAddress((void**)&w_lo, g_w_lo);

    // bf16 views over fp32 scratch
    __nv_bfloat16* qkvh = (__nv_bfloat16*)qkv;
    __nv_bfloat16* qkvl = qkvh + (size_t)T_TOK * D3;
    __nv_bfloat16* atth = (__nv_bfloat16*)attn;
    __nv_bfloat16* attl = atth + (size_t)T_TOK * DMODEL;
    __nv_bfloat16* ffh  = (__nv_bfloat16*)ff;
    __nv_bfloat16* ffl  = ffh + (size_t)T_TOK * FFDIM;

    cudaFuncSetAttribute(gemm_mma<false, false, true>,
        cudaFuncAttributeMaxDynamicSharedMemorySize, GEMM_SMEM_BYTES);
    cudaFuncSetAttribute(gemm_mma<false, true, false>,
        cudaFuncAttributeMaxDynamicSharedMemorySize, GEMM_SMEM_BYTES);
    cudaFuncSetAttribute(gemm_mma<true, false, true>,
        cudaFuncAttributeMaxDynamicSharedMemorySize, GEMM_SMEM_BYTES);
    cudaFuncSetAttribute(attn_mma,
        cudaFuncAttributeMaxDynamicSharedMemorySize, ATT_SMEM);

    const dim3 tsb(32, 8);

    // 1) qkv = x @ w_qkv + b_qkv  -> bf16 hi/lo directly
    split_kernel<<<(T_TOK * DMODEL / 4 + 255) / 256, 256>>>(x, a_hi, a_lo,
                                                            T_TOK * DMODEL / 4);
    tsplit_kernel<<<dim3(D3 / 32, DMODEL / 32), tsb>>>(w_qkv, w_hi, w_lo,
                                                       DMODEL, D3);
    gemm_mma<false, false, true><<<dim3(D3 / 128, T_TOK / 128), 256,
                                   GEMM_SMEM_BYTES>>>(
        a_hi, a_lo, w_hi, w_lo, b_qkv, nullptr, nullptr, qkvh, qkvl,
        T_TOK, D3, DMODEL);

    // 2) attention (tensor-core, emits hi/lo splits)
    attn_mma<<<512, 256, ATT_SMEM>>>(qkvh, qkvl, atth, attl);

    // 3) res1 = attn @ w_o + b_o + x
    tsplit_kernel<<<dim3(DMODEL / 32, DMODEL / 32), tsb>>>(w_o, w_hi, w_lo,
                                                           DMODEL, DMODEL);
    gemm_mma<false, true, false><<<dim3(DMODEL / 128, T_TOK / 128), 256,
                                   GEMM_SMEM_BYTES>>>(
        atth, attl, w_hi, w_lo, b_o, x, res, nullptr, nullptr,
        T_TOK, DMODEL, DMODEL);

    // 4) h = LN(res1) (+ hi/lo split)
    ln_kernel<true><<<T_TOK, 256>>>(res, g1, be1, h, a_hi, a_lo);

    // 5) ff = relu(h @ w1 + b1) -> bf16 hi/lo directly
    tsplit_kernel<<<dim3(FFDIM / 32, DMODEL / 32), tsb>>>(w1, w_hi, w_lo,
                                                          DMODEL, FFDIM);
    gemm_mma<true, false, true><<<dim3(FFDIM / 128, T_TOK / 128), 256,
                                  GEMM_SMEM_BYTES>>>(
        a_hi, a_lo, w_hi, w_lo, b1, nullptr, nullptr, ffh, ffl,
        T_TOK, FFDIM, DMODEL);

    // 6) res2 = ff @ w2 + b2 + h
    tsplit_kernel<<<dim3(DMODEL / 32, FFDIM / 32), tsb>>>(w2, w_hi, w_lo,
                                                          FFDIM, DMODEL);
    gemm_mma<false, true, false><<<dim3(DMODEL / 128, T_TOK / 128), 256,
                                   GEMM_SMEM_BYTES>>>(
        ffh, ffl, w_hi, w_lo, b2, h, res, nullptr, nullptr,
        T_TOK, DMODEL, FFDIM);

    // 7) out = LN(res2)
    ln_kernel<false><<<T_TOK, 256>>>(res, g2, be2, out, nullptr, nullptr);
}